// round 9
// baseline (speedup 1.0000x reference)
#include <cuda_runtime.h>
#include <cuda_bf16.h>
#include <cuda_fp16.h>
#include <cstdint>

#define HDIM 64
#define NODE_DIM 92
#define EDGE_DIM 41
#define KD 169
#define OUTC 128
#define PRED_H 128
#define BN_EPS 1e-5f
#define MAX_NODES 100000
#define MAX_EDGES 1600000
#define MAX_GRAPHS 4096
#define MAX_CONV 3

// edge GEMM (EW = ef @ W3): K = 48 (41 padded), N = 128
#define ECH 3
#define EASTRIDE 28
#define EAWORDS (128 * EASTRIDE)
#define EBU2 (ECH * 16 * 32)          // 1536 uint2 per layer
// node GEMM (P = h @ [W1;W2]): K = 64, N = 256
#define PCH 4
#define PASTRIDE 36
#define PAWORDS (128 * PASTRIDE)
#define PBU2 (PCH * 32 * 32)          // 4096 uint2 per layer

// ------------------------- device scratch ------------------------------------
__device__ float  g_h[MAX_NODES * HDIM];
__device__ __half g_zh[(size_t)MAX_EDGES * OUTC];   // CSR-ordered pre-BN activations
__device__ float  g_sum[OUTC];
__device__ float  g_sumsq[OUTC];
__device__ float  g_coef[2 * OUTC];
__device__ float  g_pool[MAX_GRAPHS * HDIM];
__device__ float  g_cnt[MAX_GRAPHS];
__device__ __align__(16) uint2    g_bfragE[MAX_CONV * EBU2];
__device__ __align__(16) uint2    g_bfragP[MAX_CONV * PBU2];
__device__ __align__(16) uint32_t g_hh[(size_t)MAX_NODES * 32];   // h fp16x2
__device__ __align__(16) uint32_t g_efh[(size_t)MAX_EDGES * 24];  // ef fp16x2 (48 cols)
__device__ __align__(16) uint32_t g_P[(size_t)MAX_NODES * 128];   // P1|P2 fp16x2
// CSR
__device__ int g_rowstart[MAX_NODES + 1];
__device__ int g_cursor[MAX_NODES];
__device__ int g_epos[MAX_EDGES];
__device__ int g_bsum[1024];

// ------------------------- helpers ------------------------------------------
__device__ __forceinline__ float fsig(float x) {
    float t;
    asm("tanh.approx.f32 %0, %1;" : "=f"(t) : "f"(0.5f * x));
    return fmaf(0.5f, t, 0.5f);
}
__device__ __forceinline__ float fsp(float x) {
    float t = __expf(-fabsf(x));
    return fmaxf(x, 0.f) + __logf(1.f + t);
}
__device__ __forceinline__ void mma16816(float* d, const uint32_t* a, uint2 b) {
    asm volatile("mma.sync.aligned.m16n8k16.row.col.f32.f16.f16.f32 "
                 "{%0,%1,%2,%3}, {%4,%5,%6,%7}, {%8,%9}, {%0,%1,%2,%3};"
                 : "+f"(d[0]), "+f"(d[1]), "+f"(d[2]), "+f"(d[3])
                 : "r"(a[0]), "r"(a[1]), "r"(a[2]), "r"(a[3]), "r"(b.x), "r"(b.y));
}
__device__ __forceinline__ uint32_t smem_u32(const void* p) {
    uint32_t a;
    asm("{ .reg .u64 t; cvta.to.shared.u64 t, %1; cvt.u32.u64 %0, t; }" : "=r"(a) : "l"(p));
    return a;
}
__device__ __forceinline__ void cp16(uint32_t dst, const void* src, int sz) {
    asm volatile("cp.async.cg.shared.global [%0], [%1], 16, %2;"
                 :: "r"(dst), "l"(src), "r"(sz) : "memory");
}
#define CP_COMMIT() asm volatile("cp.async.commit_group;" ::: "memory")
#define CP_WAIT0()  asm volatile("cp.async.wait_group 0;" ::: "memory")

// ------------------------- 1. node embedding --------------------------------
__global__ void __launch_bounds__(256)
emb_kernel(const float* __restrict__ nf, const float* __restrict__ Wm,
           const float* __restrict__ b, int nNodes) {
    __shared__ float sW[NODE_DIM * HDIM];
    __shared__ float sXn[8][NODE_DIM];
    for (int i = threadIdx.x; i < NODE_DIM * HDIM; i += 256) sW[i] = Wm[i];
    __syncthreads();
    int wid = threadIdx.x >> 5, lane = threadIdx.x & 31;
    int gw = (blockIdx.x * 256 + threadIdx.x) >> 5;
    int nW = (gridDim.x * 256) >> 5;
    float b0 = b[lane], b1 = b[lane + 32];
    for (int n = gw; n < nNodes; n += nW) {
        __syncwarp();
        for (int k = lane; k < NODE_DIM; k += 32) sXn[wid][k] = nf[(size_t)n * NODE_DIM + k];
        __syncwarp();
        float a0 = b0, a1 = b1;
        #pragma unroll 4
        for (int k = 0; k < NODE_DIM; k++) {
            float xv = sXn[wid][k];
            a0 = fmaf(xv, sW[k * HDIM + lane], a0);
            a1 = fmaf(xv, sW[k * HDIM + lane + 32], a1);
        }
        g_h[(size_t)n * HDIM + lane] = a0;
        g_h[(size_t)n * HDIM + lane + 32] = a1;
    }
}

__global__ void __launch_bounds__(256)
hsplit_kernel(int nNodes) {
    int idx = blockIdx.x * 256 + threadIdx.x;
    if (idx >= nNodes * 32) return;
    float2 v = ((const float2*)g_h)[idx];
    __half2 h = __floats2half2_rn(v.x, v.y);
    g_hh[idx] = *reinterpret_cast<uint32_t*>(&h);
}

__global__ void __launch_bounds__(256)
efsplit_kernel(const float* __restrict__ ef, int nEdges) {
    long long idx = (long long)blockIdx.x * 256 + threadIdx.x;
    if (idx >= (long long)nEdges * 24) return;
    int w = (int)(idx % 24);
    long long e = idx / 24;
    int c = 2 * w;
    float f0 = 0.f, f1 = 0.f;
    if (c < EDGE_DIM)     f0 = ef[e * EDGE_DIM + c];
    if (c + 1 < EDGE_DIM) f1 = ef[e * EDGE_DIM + c + 1];
    __half2 h = __floats2half2_rn(f0, f1);
    g_efh[idx] = *reinterpret_cast<uint32_t*>(&h);
}

// ------------------------- CSR build -----------------------------------------
__global__ void zero_cnt_kernel(int nNodes) {
    int i = blockIdx.x * 256 + threadIdx.x;
    if (i < nNodes) g_cursor[i] = 0;
}
__global__ void hist_kernel(const int* __restrict__ ei, int nEdges) {
    int e = blockIdx.x * 256 + threadIdx.x;
    if (e < nEdges) atomicAdd(&g_cursor[ei[e]], 1);
}
__global__ void __launch_bounds__(1024)
scan1_kernel(int n) {
    __shared__ int wsum[32];
    int tid = threadIdx.x;
    int i = blockIdx.x * 1024 + tid;
    int c = (i < n) ? g_cursor[i] : 0;
    int v = c;
    #pragma unroll
    for (int o = 1; o < 32; o <<= 1) {
        int t = __shfl_up_sync(0xffffffffu, v, o);
        if ((tid & 31) >= o) v += t;
    }
    if ((tid & 31) == 31) wsum[tid >> 5] = v;
    __syncthreads();
    if (tid < 32) {
        int s = wsum[tid];
        #pragma unroll
        for (int o = 1; o < 32; o <<= 1) {
            int t = __shfl_up_sync(0xffffffffu, s, o);
            if (tid >= o) s += t;
        }
        wsum[tid] = s;
    }
    __syncthreads();
    int incl = v + ((tid >= 32) ? wsum[(tid >> 5) - 1] : 0);
    if (i < n) g_rowstart[i] = incl - c;
    if (tid == 1023) g_bsum[blockIdx.x] = incl;
}
__global__ void __launch_bounds__(1024)
scan2_kernel(int nb) {
    __shared__ int wsum[32];
    int tid = threadIdx.x;
    int v = (tid < nb) ? g_bsum[tid] : 0;
    #pragma unroll
    for (int o = 1; o < 32; o <<= 1) {
        int t = __shfl_up_sync(0xffffffffu, v, o);
        if ((tid & 31) >= o) v += t;
    }
    if ((tid & 31) == 31) wsum[tid >> 5] = v;
    __syncthreads();
    if (tid < 32) {
        int s = wsum[tid];
        #pragma unroll
        for (int o = 1; o < 32; o <<= 1) {
            int t = __shfl_up_sync(0xffffffffu, s, o);
            if (tid >= o) s += t;
        }
        wsum[tid] = s;
    }
    __syncthreads();
    int incl = v + ((tid >= 32) ? wsum[(tid >> 5) - 1] : 0);
    if (tid < nb) g_bsum[tid] = incl;
}
__global__ void __launch_bounds__(1024)
scan3_kernel(int n, int nEdges) {
    int i = blockIdx.x * 1024 + threadIdx.x;
    if (i >= n) return;
    int off = blockIdx.x ? g_bsum[blockIdx.x - 1] : 0;
    int ex = g_rowstart[i] + off;
    g_rowstart[i] = ex;
    g_cursor[i] = ex;
    if (i == n - 1) g_rowstart[n] = nEdges;
}
__global__ void scatter_kernel(const int* __restrict__ ei, int nEdges) {
    int e = blockIdx.x * 256 + threadIdx.x;
    if (e >= nEdges) return;
    g_epos[e] = atomicAdd(&g_cursor[ei[e]], 1);
}

// ------------------------- B fragment precompute (all layers) ---------------
__global__ void __launch_bounds__(256)
bfragE_kernel(const float* __restrict__ W, int total) {
    int idx = blockIdx.x * 256 + threadIdx.x;
    if (idx >= total) return;
    int l = idx / EBU2, r = idx % EBU2;
    int lane = r & 31, ntg = (r >> 5) & 15, bi = r >> 9;
    const float* Wl = W + (size_t)l * KD * OUTC;
    int n = ntg * 8 + (lane >> 2);
    int k0 = bi * 16 + (lane & 3) * 2;
    uint32_t out[2];
    #pragma unroll
    for (int half = 0; half < 2; half++) {
        int ka = k0 + half * 8, kb = ka + 1;
        float w0 = (ka < EDGE_DIM) ? Wl[(128 + ka) * OUTC + n] : 0.f;
        float w1 = (kb < EDGE_DIM) ? Wl[(128 + kb) * OUTC + n] : 0.f;
        __half2 h = __floats2half2_rn(w0, w1);
        out[half] = *reinterpret_cast<uint32_t*>(&h);
    }
    g_bfragE[idx] = make_uint2(out[0], out[1]);
}

__global__ void __launch_bounds__(256)
bfragP_kernel(const float* __restrict__ W, int total) {
    int idx = blockIdx.x * 256 + threadIdx.x;
    if (idx >= total) return;
    int l = idx / PBU2, r = idx % PBU2;
    int lane = r & 31, ntg = (r >> 5) & 31, bi = r >> 10;
    const float* Wl = W + (size_t)l * KD * OUTC;
    int n = ntg * 8 + (lane >> 2);          // 0..255
    int k0 = bi * 16 + (lane & 3) * 2;      // < 64
    uint32_t out[2];
    #pragma unroll
    for (int half = 0; half < 2; half++) {
        int k = k0 + half * 8;
        float w0, w1;
        if (n < 128) { w0 = Wl[k * OUTC + n];           w1 = Wl[(k + 1) * OUTC + n]; }
        else         { w0 = Wl[(64 + k) * OUTC + n - 128]; w1 = Wl[(65 + k) * OUTC + n - 128]; }
        __half2 h = __floats2half2_rn(w0, w1);
        out[half] = *reinterpret_cast<uint32_t*>(&h);
    }
    g_bfragP[idx] = make_uint2(out[0], out[1]);
}

// ------------------------- P = h @ [W1;W2]  (node GEMM) ---------------------
__global__ void __launch_bounds__(256, 2)
pgemm_kernel(int l, int nNodes, int nTiles) {
    extern __shared__ uint32_t sm[];
    uint32_t* sA = sm;                       // [128][PASTRIDE]
    uint2*    sB = (uint2*)(sm + PAWORDS);   // PBU2

    const int tid = threadIdx.x, wid = tid >> 5, lane = tid & 31;
    const int q = lane & 3, r8 = lane >> 2;
    const int wm = wid & 3, wn = wid >> 2;   // wn in {0,1}

    const uint2* bf = g_bfragP + (size_t)l * PBU2;
    for (int i = tid; i < PBU2 / 2; i += 256)
        ((uint4*)sB)[i] = ((const uint4*)bf)[i];

    for (int t = blockIdx.x; t < nTiles; t += gridDim.x) {
        {   // gather: stream hh rows
            int j = tid, row = j >> 1, half = j & 1;
            int n = (t << 7) + row;
            int nc = (n < nNodes) ? n : 0;
            int sz = (n < nNodes) ? 16 : 0;
            const char* hs = (const char*)(g_hh + (size_t)nc * 32 + half * 16);
            uint32_t d = smem_u32(sA + row * PASTRIDE + half * 16);
            #pragma unroll
            for (int i = 0; i < 4; i++) cp16(d + i * 16, hs + i * 16, sz);
            CP_COMMIT();
        }
        CP_WAIT0();
        __syncthreads();

        const uint32_t* aRow0 = sA + (wm * 32 + r8) * PASTRIDE;
        #pragma unroll 1
        for (int nh = 0; nh < 2; nh++) {
            float acc[2][8][4];
            #pragma unroll
            for (int mt = 0; mt < 2; mt++)
                #pragma unroll
                for (int nt = 0; nt < 8; nt++)
                    #pragma unroll
                    for (int jj = 0; jj < 4; jj++) acc[mt][nt][jj] = 0.f;
            const uint2* bBase = sB + (nh * 16 + wn * 8) * 32 + lane;
            #pragma unroll
            for (int bi = 0; bi < PCH; bi++) {
                uint2 b[8];
                const uint2* bp = bBase + bi * 1024;
                #pragma unroll
                for (int nt = 0; nt < 8; nt++) b[nt] = bp[nt * 32];
                uint32_t a[2][4];
                int aw = bi * 8 + q;
                #pragma unroll
                for (int mt = 0; mt < 2; mt++) {
                    const uint32_t* ar = aRow0 + mt * 16 * PASTRIDE;
                    a[mt][0] = ar[aw];       a[mt][1] = ar[8 * PASTRIDE + aw];
                    a[mt][2] = ar[aw + 4];   a[mt][3] = ar[8 * PASTRIDE + aw + 4];
                }
                #pragma unroll
                for (int nt = 0; nt < 8; nt++) {
                    mma16816(acc[0][nt], a[0], b[nt]);
                    mma16816(acc[1][nt], a[1], b[nt]);
                }
            }
            #pragma unroll
            for (int mt = 0; mt < 2; mt++)
                #pragma unroll
                for (int hf = 0; hf < 2; hf++) {
                    int n = (t << 7) + wm * 32 + mt * 16 + hf * 8 + r8;
                    if (n < nNodes) {
                        uint32_t* base = g_P + (size_t)n * 128 + nh * 64 + wn * 32 + q;
                        #pragma unroll
                        for (int nt = 0; nt < 8; nt++) {
                            __half2 h = __floats2half2_rn(acc[mt][nt][2 * hf],
                                                          acc[mt][nt][2 * hf + 1]);
                            base[nt * 4] = *reinterpret_cast<uint32_t*>(&h);
                        }
                    }
                }
        }
        __syncthreads();
    }
}

// ------------------------- EW GEMM + combine + BN stats ---------------------
__device__ __forceinline__ void gatherEf(uint32_t* sA, int nEdges, int t, int nTiles) {
    if (t >= nTiles) return;
    int j = threadIdx.x, row = j >> 1, half = j & 1;
    int e = (t << 7) + row;
    int ec = (e < nEdges) ? e : 0;
    int sz = (e < nEdges) ? 16 : 0;
    const char* es = (const char*)(g_efh + (size_t)ec * 24 + half * 12);
    uint32_t d = smem_u32(sA + row * EASTRIDE + half * 12);
    #pragma unroll
    for (int i = 0; i < 3; i++) cp16(d + i * 16, es + i * 16, sz);
    CP_COMMIT();
}

__global__ void __launch_bounds__(256, 2)
ewz_kernel(const int* __restrict__ ei, int l, int nEdges, int nTiles) {
    __shared__ uint32_t sA0[EAWORDS];
    __shared__ uint32_t sA1[EAWORDS];
    __shared__ uint2    sB[EBU2];

    const int tid = threadIdx.x, wid = tid >> 5, lane = tid & 31;
    const int q = lane & 3, r8 = lane >> 2;
    const int wm = wid & 3, wn = wid >> 2;

    gatherEf(sA0, nEdges, blockIdx.x, nTiles);
    const uint2* bf = g_bfragE + (size_t)l * EBU2;
    for (int i = tid; i < EBU2 / 2; i += 256)
        ((uint4*)sB)[i] = ((const uint4*)bf)[i];

    float ssum[16], ssq[16];
    #pragma unroll
    for (int j = 0; j < 16; j++) { ssum[j] = 0.f; ssq[j] = 0.f; }

    CP_WAIT0();
    __syncthreads();

    const uint2* bBase = sB + (wn * 8) * 32 + lane;
    int par = 0;
    for (int t = blockIdx.x; t < nTiles; t += gridDim.x) {
        const uint32_t* cur = par ? sA1 : sA0;
        const uint32_t* aRow0 = cur + (wm * 32 + r8) * EASTRIDE;
        const int e0 = t << 7;

        int pe[4], se[4], de[4];
        #pragma unroll
        for (int mt = 0; mt < 2; mt++)
            #pragma unroll
            for (int hf = 0; hf < 2; hf++) {
                int i = mt * 2 + hf;
                int e = e0 + wm * 32 + mt * 16 + hf * 8 + r8;
                if (e < nEdges) {
                    pe[i] = __ldg(&g_epos[e]);
                    se[i] = __ldg(&ei[e]);
                    de[i] = __ldg(&ei[nEdges + e]);
                } else { pe[i] = -1; se[i] = 0; de[i] = 0; }
            }

        #pragma unroll 1
        for (int nh = 0; nh < 2; nh++) {
            float acc[2][4][4];
            #pragma unroll
            for (int mt = 0; mt < 2; mt++)
                #pragma unroll
                for (int n4 = 0; n4 < 4; n4++)
                    #pragma unroll
                    for (int jj = 0; jj < 4; jj++) acc[mt][n4][jj] = 0.f;
            #pragma unroll
            for (int bi = 0; bi < ECH; bi++) {
                uint2 b[4];
                const uint2* bp = bBase + bi * 512 + nh * 128;
                #pragma unroll
                for (int n4 = 0; n4 < 4; n4++) b[n4] = bp[n4 * 32];
                uint32_t a[2][4];
                int aw = bi * 8 + q;
                #pragma unroll
                for (int mt = 0; mt < 2; mt++) {
                    const uint32_t* ar = aRow0 + mt * 16 * EASTRIDE;
                    a[mt][0] = ar[aw];       a[mt][1] = ar[8 * EASTRIDE + aw];
                    a[mt][2] = ar[aw + 4];   a[mt][3] = ar[8 * EASTRIDE + aw + 4];
                }
                #pragma unroll
                for (int n4 = 0; n4 < 4; n4++) {
                    mma16816(acc[0][n4], a[0], b[n4]);
                    mma16816(acc[1][n4], a[1], b[n4]);
                }
            }
            if (nh == 1)  // after last A reads: prefetch next tile into other buffer
                gatherEf(par ? sA0 : sA1, nEdges, t + gridDim.x, nTiles);

            // combine with P1[src] + P2[dst], stats, write z (CSR position)
            #pragma unroll
            for (int mt = 0; mt < 2; mt++)
                #pragma unroll
                for (int hf = 0; hf < 2; hf++) {
                    int i = mt * 2 + hf;
                    if (pe[i] < 0) continue;
                    const uint32_t* p1 = g_P + (size_t)se[i] * 128 + wn * 32 + nh * 16 + q;
                    const uint32_t* p2 = g_P + (size_t)de[i] * 128 + 64 + wn * 32 + nh * 16 + q;
                    __half* zb = g_zh + (size_t)pe[i] * OUTC + wn * 64 + nh * 32 + 2 * q;
                    #pragma unroll
                    for (int n4 = 0; n4 < 4; n4++) {
                        uint32_t w1 = p1[n4 * 4], w2 = p2[n4 * 4];
                        float2 f1 = __half22float2(*reinterpret_cast<__half2*>(&w1));
                        float2 f2 = __half22float2(*reinterpret_cast<__half2*>(&w2));
                        float z0 = acc[mt][n4][2 * hf]     + f1.x + f2.x;
                        float z1 = acc[mt][n4][2 * hf + 1] + f1.y + f2.y;
                        int s = nh * 8 + n4 * 2;
                        ssum[s]     += z0;  ssq[s]     += z0 * z0;
                        ssum[s + 1] += z1;  ssq[s + 1] += z1 * z1;
                        __half2 h = __floats2half2_rn(z0, z1);
                        *(uint32_t*)(zb + n4 * 8) = *reinterpret_cast<uint32_t*>(&h);
                    }
                }
        }
        CP_WAIT0();
        __syncthreads();
        par ^= 1;
    }

    #pragma unroll
    for (int j = 0; j < 16; j++) {
        #pragma unroll
        for (int ofs = 4; ofs < 32; ofs <<= 1) {
            ssum[j] += __shfl_xor_sync(0xffffffffu, ssum[j], ofs);
            ssq[j]  += __shfl_xor_sync(0xffffffffu, ssq[j], ofs);
        }
    }
    if (lane < 4) {
        #pragma unroll
        for (int nh = 0; nh < 2; nh++)
            #pragma unroll
            for (int n4 = 0; n4 < 4; n4++)
                #pragma unroll
                for (int jj = 0; jj < 2; jj++) {
                    int col = wn * 64 + nh * 32 + n4 * 8 + 2 * lane + jj;
                    atomicAdd(&g_sum[col],   ssum[nh * 8 + n4 * 2 + jj]);
                    atomicAdd(&g_sumsq[col], ssq[nh * 8 + n4 * 2 + jj]);
                }
    }
}

// ------------------------- BN coefficients (self-zeroing) -------------------
__global__ void bn_coef_kernel(const float* __restrict__ gamma,
                               const float* __restrict__ beta, float invE) {
    int c = threadIdx.x;
    float s = g_sum[c], ss = g_sumsq[c];
    float mean = s * invE;
    float var  = fmaf(-mean, mean, ss * invE);
    float a    = gamma[c] * rsqrtf(var + BN_EPS);
    g_coef[c]        = a;
    g_coef[OUTC + c] = fmaf(-mean, a, beta[c]);
    g_sum[c] = 0.f;
    g_sumsq[c] = 0.f;
}

// ------------------------- CSR gate: streaming z ----------------------------
__global__ void __launch_bounds__(256)
csr_gate_kernel(const int* __restrict__ gidArr, int nNodes, int doPool) {
    int gw = blockIdx.x * 8 + (threadIdx.x >> 5);
    if (gw >= nNodes) return;
    int lane = threadIdx.x & 31;

    float sa0 = g_coef[2 * lane],             sa1 = g_coef[2 * lane + 1];
    float ha0 = g_coef[OUTC + 2 * lane],      ha1 = g_coef[OUTC + 2 * lane + 1];
    float sb0 = g_coef[64 + 2 * lane],        sb1 = g_coef[64 + 2 * lane + 1];
    float hb0 = g_coef[OUTC + 64 + 2 * lane], hb1 = g_coef[OUTC + 64 + 2 * lane + 1];

    int beg = g_rowstart[gw], end = g_rowstart[gw + 1];
    float a0 = 0.f, a1 = 0.f;
    const uint32_t* zr = (const uint32_t*)(g_zh) + (size_t)beg * 64;
    #pragma unroll 2
    for (int i = beg; i < end; i++, zr += 64) {
        uint32_t A = zr[lane], B = zr[32 + lane];
        __half2 ha = *reinterpret_cast<__half2*>(&A);
        __half2 hb = *reinterpret_cast<__half2*>(&B);
        float na0 = fmaf(__low2float(ha),  sa0, ha0);
        float na1 = fmaf(__high2float(ha), sa1, ha1);
        float nb0 = fmaf(__low2float(hb),  sb0, hb0);
        float nb1 = fmaf(__high2float(hb), sb1, hb1);
        a0 += fsig(na0) * fsp(nb0);
        a1 += fsig(na1) * fsp(nb1);
    }
    float2* hp = (float2*)(g_h + (size_t)gw * HDIM) + lane;
    float2 hv = *hp;
    hv.x += a0; hv.y += a1;
    *hp = hv;
    __half2 hh = __floats2half2_rn(hv.x, hv.y);
    g_hh[(size_t)gw * 32 + lane] = *reinterpret_cast<uint32_t*>(&hh);
    if (doPool) {
        int g = gidArr[gw];
        float* pr = g_pool + (size_t)g * HDIM + 2 * lane;
        asm volatile("red.global.add.v2.f32 [%0], {%1, %2};"
                     :: "l"(pr), "f"(hv.x), "f"(hv.y) : "memory");
        if (lane == 0) atomicAdd(&g_cnt[g], 1.0f);
    }
}

// ------------------------- prediction head (self-zeroing pool) --------------
__global__ void __launch_bounds__(PRED_H)
head_kernel(const float* __restrict__ fcW, const float* __restrict__ fcb,
            const float* __restrict__ outW, const float* __restrict__ outb,
            float* __restrict__ out) {
    __shared__ float sp[HDIM];
    __shared__ float red[PRED_H];
    int g = blockIdx.x, t = threadIdx.x;
    if (t < HDIM) {
        float c = g_cnt[g];
        sp[t] = g_pool[(size_t)g * HDIM + t] / fmaxf(c, 1.0f);
    }
    __syncthreads();
    float acc = fcb[t];
    #pragma unroll
    for (int k = 0; k < HDIM; k++) acc = fmaf(sp[k], fcW[k * PRED_H + t], acc);
    red[t] = fmaxf(acc, 0.f) + log1pf(expf(-fabsf(acc)));
    red[t] *= outW[t];
    __syncthreads();
    for (int sft = PRED_H / 2; sft > 0; sft >>= 1) {
        if (t < sft) red[t] += red[t + sft];
        __syncthreads();
    }
    if (t == 0) out[g] = red[0] + outb[0];
    __syncthreads();
    if (t < HDIM) g_pool[(size_t)g * HDIM + t] = 0.f;
    if (t == HDIM) g_cnt[g] = 0.f;
}

// ------------------------- launch -------------------------------------------
extern "C" void kernel_launch(void* const* d_in, const int* in_sizes, int n_in,
                              void* d_out, int out_size) {
    const float* node_feats = (const float*)d_in[0];
    const int*   edge_index = (const int*)d_in[1];
    const float* edge_feats = (const float*)d_in[2];
    const int*   graph_id   = (const int*)d_in[3];
    const float* emb_W      = (const float*)d_in[4];
    const float* emb_b      = (const float*)d_in[5];
    const float* conv_W     = (const float*)d_in[6];
    // d_in[7] = conv_b: zeros; constant bias cancels exactly in BN.
    const float* bn_gamma   = (const float*)d_in[8];
    const float* bn_beta    = (const float*)d_in[9];
    const float* fc_W       = (const float*)d_in[10];
    const float* fc_b       = (const float*)d_in[11];
    const float* out_W      = (const float*)d_in[12];
    const float* out_b      = (const float*)d_in[13];

    int nNodes  = in_sizes[0] / NODE_DIM;
    int nEdges  = in_sizes[1] / 2;
    int nConv   = in_sizes[6] / (KD * OUTC);

    int nsm = 148;
    cudaDeviceGetAttribute(&nsm, cudaDevAttrMultiProcessorCount, 0);

    size_t pSmem = (size_t)(PAWORDS + 2 * PBU2) * 4;  // 51200 B
    cudaFuncSetAttribute(pgemm_kernel,
                         cudaFuncAttributeMaxDynamicSharedMemorySize, (int)pSmem);

    emb_kernel<<<2048, 256>>>(node_feats, emb_W, emb_b, nNodes);
    hsplit_kernel<<<(nNodes * 32 + 255) / 256, 256>>>(nNodes);
    {
        long long tot = (long long)nEdges * 24;
        efsplit_kernel<<<(int)((tot + 255) / 256), 256>>>(edge_feats, nEdges);
    }

    // CSR build
    int eb = (nEdges + 255) / 256;
    int nb1 = (nNodes + 1023) / 1024;
    zero_cnt_kernel<<<(nNodes + 255) / 256, 256>>>(nNodes);
    hist_kernel<<<eb, 256>>>(edge_index, nEdges);
    scan1_kernel<<<nb1, 1024>>>(nNodes);
    scan2_kernel<<<1, 1024>>>(nb1);
    scan3_kernel<<<nb1, 1024>>>(nNodes, nEdges);
    scatter_kernel<<<eb, 256>>>(edge_index, nEdges);

    // all-layer B fragments
    bfragE_kernel<<<(nConv * EBU2 + 255) / 256, 256>>>(conv_W, nConv * EBU2);
    bfragP_kernel<<<(nConv * PBU2 + 255) / 256, 256>>>(conv_W, nConv * PBU2);

    int eTiles = (nEdges + 127) / 128;
    int pTiles = (nNodes + 127) / 128;
    float invE = 1.0f / (float)nEdges;
    int gateBlocks = (nNodes + 7) / 8;
    for (int l = 0; l < nConv; l++) {
        pgemm_kernel<<<2 * nsm, 256, pSmem>>>(l, nNodes, pTiles);
        ewz_kernel<<<2 * nsm, 256>>>(edge_index, l, nEdges, eTiles);
        bn_coef_kernel<<<1, OUTC>>>(bn_gamma + l * OUTC, bn_beta + l * OUTC, invE);
        csr_gate_kernel<<<gateBlocks, 256>>>(graph_id, nNodes, l == nConv - 1);
    }

    head_kernel<<<out_size, PRED_H>>>(fc_W, fc_b, out_W, out_b, (float*)d_out);
}

// round 10
// speedup vs baseline: 1.5728x; 1.5728x over previous
#include <cuda_runtime.h>
#include <cuda_bf16.h>
#include <cuda_fp16.h>
#include <cstdint>

#define HDIM 64
#define NODE_DIM 92
#define EDGE_DIM 41
#define KD 169            // 2H + EDGE_DIM
#define OUTC 128          // 2H
#define PRED_H 128
#define BN_EPS 1e-5f
#define MAX_NODES 100000
#define MAX_EDGES 1600000
#define MAX_GRAPHS 4096
#define MAX_CONV 3

#define NCH 11            // k16 chunks (K=176 padded)
#define ASTRIDE 92        // A smem row stride (u32 words): 88 data + 4 pad
#define AWORDS (128 * ASTRIDE)               // 47104 B
#define BU2    (NCH * 16 * 32)               // 5632 uint2 = 45056 B
#define SMEM_WORDS (AWORDS + 2 * BU2)        // 92160 B -> 2 CTAs/SM

// ------------------------- device scratch ------------------------------------
__device__ float  g_h[MAX_NODES * HDIM];
__device__ __half g_zh[(size_t)MAX_EDGES * OUTC];   // CSR-permuted pre-BN activations
__device__ float  g_sum[OUTC];
__device__ float  g_sumsq[OUTC];
__device__ float  g_coef[2 * OUTC];
__device__ float  g_pool[MAX_GRAPHS * HDIM];
__device__ float  g_cnt[MAX_GRAPHS];
__device__ __align__(16) uint2    g_bfrag[MAX_CONV * BU2];
__device__ __align__(16) uint32_t g_hh[(size_t)MAX_NODES * 32];   // h as fp16x2
__device__ __align__(16) uint32_t g_efh[(size_t)MAX_EDGES * 24];  // ef as fp16x2
// CSR
__device__ int g_rowstart[MAX_NODES + 1];
__device__ int g_cursor[MAX_NODES];
__device__ int g_epos[MAX_EDGES];                   // edge -> CSR position
__device__ int g_bsum[1024];

// ------------------------- helpers ------------------------------------------
__device__ __forceinline__ float fsig(float x) {
    float t;
    asm("tanh.approx.f32 %0, %1;" : "=f"(t) : "f"(0.5f * x));
    return fmaf(0.5f, t, 0.5f);
}
__device__ __forceinline__ float fsp(float x) {
    float t = __expf(-fabsf(x));
    return fmaxf(x, 0.f) + __logf(1.f + t);
}

__device__ __forceinline__ void mma16816(float* d, const uint32_t* a, uint2 b) {
    asm volatile("mma.sync.aligned.m16n8k16.row.col.f32.f16.f16.f32 "
                 "{%0,%1,%2,%3}, {%4,%5,%6,%7}, {%8,%9}, {%0,%1,%2,%3};"
                 : "+f"(d[0]), "+f"(d[1]), "+f"(d[2]), "+f"(d[3])
                 : "r"(a[0]), "r"(a[1]), "r"(a[2]), "r"(a[3]), "r"(b.x), "r"(b.y));
}
__device__ __forceinline__ uint32_t smem_u32(const void* p) {
    uint32_t a;
    asm("{ .reg .u64 t; cvta.to.shared.u64 t, %1; cvt.u32.u64 %0, t; }" : "=r"(a) : "l"(p));
    return a;
}
__device__ __forceinline__ void cp16(uint32_t dst, const void* src, int sz) {
    asm volatile("cp.async.cg.shared.global [%0], [%1], 16, %2;"
                 :: "r"(dst), "l"(src), "r"(sz) : "memory");
}
#define CP_COMMIT() asm volatile("cp.async.commit_group;" ::: "memory")
#define CP_WAIT0()  asm volatile("cp.async.wait_group 0;" ::: "memory")

// ------------------------- 1. node embedding (writes g_h + g_hh) ------------
__global__ void __launch_bounds__(256)
emb_kernel(const float* __restrict__ nf, const float* __restrict__ Wm,
           const float* __restrict__ b, int nNodes) {
    __shared__ float sW[NODE_DIM * HDIM];
    __shared__ float sXn[8][NODE_DIM];
    for (int i = threadIdx.x; i < NODE_DIM * HDIM; i += 256) sW[i] = Wm[i];
    __syncthreads();
    int wid = threadIdx.x >> 5, lane = threadIdx.x & 31;
    int gw = (blockIdx.x * 256 + threadIdx.x) >> 5;
    int nW = (gridDim.x * 256) >> 5;
    float b0 = b[2 * lane], b1 = b[2 * lane + 1];
    for (int n = gw; n < nNodes; n += nW) {
        __syncwarp();
        for (int k = lane; k < NODE_DIM; k += 32) sXn[wid][k] = nf[(size_t)n * NODE_DIM + k];
        __syncwarp();
        float a0 = b0, a1 = b1;
        #pragma unroll 4
        for (int k = 0; k < NODE_DIM; k++) {
            float xv = sXn[wid][k];
            float2 w = ((const float2*)sW)[k * 32 + lane];
            a0 = fmaf(xv, w.x, a0);
            a1 = fmaf(xv, w.y, a1);
        }
        ((float2*)(g_h + (size_t)n * HDIM))[lane] = make_float2(a0, a1);
        __half2 h = __floats2half2_rn(a0, a1);
        g_hh[(size_t)n * 32 + lane] = *reinterpret_cast<uint32_t*>(&h);
    }
}

__global__ void __launch_bounds__(256)
efsplit_kernel(const float* __restrict__ ef, int nEdges) {
    long long idx = (long long)blockIdx.x * 256 + threadIdx.x;
    if (idx >= (long long)nEdges * 24) return;
    int w = (int)(idx % 24);
    long long e = idx / 24;
    int c = 2 * w;
    float f0 = 0.f, f1 = 0.f;
    if (c < EDGE_DIM)     f0 = ef[e * EDGE_DIM + c];
    if (c + 1 < EDGE_DIM) f1 = ef[e * EDGE_DIM + c + 1];
    __half2 h = __floats2half2_rn(f0, f1);
    g_efh[idx] = *reinterpret_cast<uint32_t*>(&h);
}

// ------------------------- CSR build -----------------------------------------
__global__ void zero_cnt_kernel(int nNodes) {
    int i = blockIdx.x * 256 + threadIdx.x;
    if (i < nNodes) g_cursor[i] = 0;
}
__global__ void hist_kernel(const int* __restrict__ ei, int nEdges) {
    int e = blockIdx.x * 256 + threadIdx.x;
    if (e < nEdges) atomicAdd(&g_cursor[ei[e]], 1);
}
__global__ void __launch_bounds__(1024)
scan1_kernel(int n) {
    __shared__ int wsum[32];
    int tid = threadIdx.x;
    int i = blockIdx.x * 1024 + tid;
    int c = (i < n) ? g_cursor[i] : 0;
    int v = c;
    #pragma unroll
    for (int o = 1; o < 32; o <<= 1) {
        int t = __shfl_up_sync(0xffffffffu, v, o);
        if ((tid & 31) >= o) v += t;
    }
    if ((tid & 31) == 31) wsum[tid >> 5] = v;
    __syncthreads();
    if (tid < 32) {
        int s = wsum[tid];
        #pragma unroll
        for (int o = 1; o < 32; o <<= 1) {
            int t = __shfl_up_sync(0xffffffffu, s, o);
            if (tid >= o) s += t;
        }
        wsum[tid] = s;
    }
    __syncthreads();
    int incl = v + ((tid >= 32) ? wsum[(tid >> 5) - 1] : 0);
    if (i < n) g_rowstart[i] = incl - c;
    if (tid == 1023) g_bsum[blockIdx.x] = incl;
}
__global__ void __launch_bounds__(1024)
scan2_kernel(int nb) {
    __shared__ int wsum[32];
    int tid = threadIdx.x;
    int v = (tid < nb) ? g_bsum[tid] : 0;
    #pragma unroll
    for (int o = 1; o < 32; o <<= 1) {
        int t = __shfl_up_sync(0xffffffffu, v, o);
        if ((tid & 31) >= o) v += t;
    }
    if ((tid & 31) == 31) wsum[tid >> 5] = v;
    __syncthreads();
    if (tid < 32) {
        int s = wsum[tid];
        #pragma unroll
        for (int o = 1; o < 32; o <<= 1) {
            int t = __shfl_up_sync(0xffffffffu, s, o);
            if (tid >= o) s += t;
        }
        wsum[tid] = s;
    }
    __syncthreads();
    int incl = v + ((tid >= 32) ? wsum[(tid >> 5) - 1] : 0);
    if (tid < nb) g_bsum[tid] = incl;
}
__global__ void __launch_bounds__(1024)
scan3_kernel(int n, int nEdges) {
    int i = blockIdx.x * 1024 + threadIdx.x;
    if (i >= n) return;
    int off = blockIdx.x ? g_bsum[blockIdx.x - 1] : 0;
    int ex = g_rowstart[i] + off;
    g_rowstart[i] = ex;
    g_cursor[i] = ex;
    if (i == n - 1) g_rowstart[n] = nEdges;
}
__global__ void scatter_kernel(const int* __restrict__ ei, int nEdges) {
    int e = blockIdx.x * 256 + threadIdx.x;
    if (e >= nEdges) return;
    g_epos[e] = atomicAdd(&g_cursor[ei[e]], 1);
}

// ------------------------- 2a. B fragments, all layers ----------------------
__global__ void __launch_bounds__(256)
bfrag_kernel(const float* __restrict__ W, int total) {
    int idx = blockIdx.x * 256 + threadIdx.x;
    if (idx >= total) return;
    int l = idx / BU2, r = idx % BU2;
    int lane = r & 31;
    int nt   = (r >> 5) & 15;
    int bi   = r >> 9;                // 0..10
    const float* Wl = W + (size_t)l * KD * OUTC;
    int n    = nt * 8 + (lane >> 2);
    int k0   = bi * 16 + (lane & 3) * 2;
    uint32_t out[2];
    #pragma unroll
    for (int half = 0; half < 2; half++) {
        float w0 = 0.f, w1 = 0.f;
        int ka = k0 + half * 8, kb = ka + 1;
        if (ka < KD) w0 = Wl[ka * OUTC + n];
        if (kb < KD) w1 = Wl[kb * OUTC + n];
        __half2 h = __floats2half2_rn(w0, w1);
        out[half] = *reinterpret_cast<uint32_t*>(&h);
    }
    g_bfrag[idx] = make_uint2(out[0], out[1]);
}

// ------------------------- 2b. conv edge GEMM (2 CTAs/SM, N-split) ----------
__device__ __forceinline__ void gatherAsync(uint32_t* sA, const int* __restrict__ ei,
                                            int nEdges, int t, int nTiles) {
    if (t >= nTiles) return;
    int j = threadIdx.x;
    int row = j >> 1, half = j & 1;
    int e = (t << 7) + row;
    bool valid = e < nEdges;
    int ec = valid ? e : 0;
    int sz = valid ? 16 : 0;
    int node = ei[half ? nEdges + ec : ec];
    const char* hs = (const char*)(g_hh + (size_t)node * 32);
    uint32_t* rw = sA + row * ASTRIDE;
    uint32_t dh = smem_u32(rw + half * 32);
    #pragma unroll
    for (int i = 0; i < 8; i++) cp16(dh + i * 16, hs + i * 16, sz);
    const char* es = (const char*)(g_efh + (size_t)ec * 24 + half * 12);
    uint32_t de = smem_u32(rw + 64 + half * 12);
    #pragma unroll
    for (int i = 0; i < 3; i++) cp16(de + i * 16, es + i * 16, sz);
    CP_COMMIT();
}

__device__ __forceinline__ void kloop(float acc[2][4][4], const uint32_t* aRow0,
                                      const uint2* bBase, int nh, int q) {
    #pragma unroll 1
    for (int bi = 0; bi < NCH; bi++) {
        uint2 b[4];
        const uint2* bp = bBase + bi * 512 + nh * 128;
        #pragma unroll
        for (int n4 = 0; n4 < 4; n4++) b[n4] = bp[n4 * 32];
        uint32_t a[2][4];
        int aw = bi * 8 + q;
        #pragma unroll
        for (int mt = 0; mt < 2; mt++) {
            const uint32_t* ar = aRow0 + mt * 16 * ASTRIDE;
            a[mt][0] = ar[aw];         a[mt][1] = ar[8 * ASTRIDE + aw];
            a[mt][2] = ar[aw + 4];     a[mt][3] = ar[8 * ASTRIDE + aw + 4];
        }
        #pragma unroll
        for (int n4 = 0; n4 < 4; n4++) {
            mma16816(acc[0][n4], a[0], b[n4]);
            mma16816(acc[1][n4], a[1], b[n4]);
        }
    }
}

__device__ __forceinline__ void statsEpi(float acc[2][4][4], int nh, const int* pe,
                                         int wn, int q, float* ssum, float* ssq) {
    #pragma unroll
    for (int mt = 0; mt < 2; mt++)
        #pragma unroll
        for (int n4 = 0; n4 < 4; n4++) {
            float c0 = acc[mt][n4][0], c1 = acc[mt][n4][1];
            float c2 = acc[mt][n4][2], c3 = acc[mt][n4][3];
            int s = nh * 8 + n4 * 2;
            ssum[s]     += c0 + c2;   ssum[s + 1] += c1 + c3;
            ssq[s]      += c0 * c0 + c2 * c2;
            ssq[s + 1]  += c1 * c1 + c3 * c3;
        }
    #pragma unroll
    for (int mt = 0; mt < 2; mt++)
        #pragma unroll
        for (int hf = 0; hf < 2; hf++) {
            int p = pe[mt * 2 + hf];
            if (p >= 0) {
                __half* base = g_zh + (size_t)p * OUTC + wn * 64 + nh * 32 + 2 * q;
                #pragma unroll
                for (int n4 = 0; n4 < 4; n4++) {
                    __half2 h = __floats2half2_rn(acc[mt][n4][2 * hf],
                                                  acc[mt][n4][2 * hf + 1]);
                    *(uint32_t*)(base + n4 * 8) = *reinterpret_cast<uint32_t*>(&h);
                }
            }
        }
}

__global__ void __launch_bounds__(256, 2)
conv_mma_kernel(const int* __restrict__ ei, int l, int nEdges, int nTiles) {
    extern __shared__ uint32_t sm[];
    uint32_t* sA = sm;
    uint2*    sB = (uint2*)(sm + AWORDS);

    const int tid = threadIdx.x, wid = tid >> 5, lane = tid & 31;
    const int q = lane & 3, r8 = lane >> 2;
    const int wm = wid & 3, wn = wid >> 2;

    gatherAsync(sA, ei, nEdges, blockIdx.x, nTiles);
    const uint2* bf = g_bfrag + (size_t)l * BU2;
    for (int i = tid; i < BU2 / 2; i += 256)
        ((uint4*)sB)[i] = ((const uint4*)bf)[i];

    float ssum[16], ssq[16];
    #pragma unroll
    for (int j = 0; j < 16; j++) { ssum[j] = 0.f; ssq[j] = 0.f; }

    CP_WAIT0();
    __syncthreads();

    const uint32_t* aRow0 = sA + (wm * 32 + r8) * ASTRIDE;
    const uint2*    bBase = sB + (wn * 8) * 32 + lane;

    for (int t = blockIdx.x; t < nTiles; t += gridDim.x) {
        const int e0 = t << 7;
        int pe[4];
        #pragma unroll
        for (int mt = 0; mt < 2; mt++)
            #pragma unroll
            for (int hf = 0; hf < 2; hf++) {
                int e = e0 + wm * 32 + mt * 16 + hf * 8 + r8;
                pe[mt * 2 + hf] = (e < nEdges) ? __ldg(&g_epos[e]) : -1;
            }
        {   // N half 0
            float acc[2][4][4];
            #pragma unroll
            for (int mt = 0; mt < 2; mt++)
                #pragma unroll
                for (int n4 = 0; n4 < 4; n4++)
                    #pragma unroll
                    for (int jj = 0; jj < 4; jj++) acc[mt][n4][jj] = 0.f;
            kloop(acc, aRow0, bBase, 0, q);
            statsEpi(acc, 0, pe, wn, q, ssum, ssq);
        }
        {   // N half 1 (+ prefetch next tile between MMA and epilogue)
            float acc[2][4][4];
            #pragma unroll
            for (int mt = 0; mt < 2; mt++)
                #pragma unroll
                for (int n4 = 0; n4 < 4; n4++)
                    #pragma unroll
                    for (int jj = 0; jj < 4; jj++) acc[mt][n4][jj] = 0.f;
            kloop(acc, aRow0, bBase, 1, q);
            __syncthreads();
            gatherAsync(sA, ei, nEdges, t + gridDim.x, nTiles);
            statsEpi(acc, 1, pe, wn, q, ssum, ssq);
        }
        CP_WAIT0();
        __syncthreads();
    }

    #pragma unroll
    for (int j = 0; j < 16; j++) {
        #pragma unroll
        for (int ofs = 4; ofs < 32; ofs <<= 1) {
            ssum[j] += __shfl_xor_sync(0xffffffffu, ssum[j], ofs);
            ssq[j]  += __shfl_xor_sync(0xffffffffu, ssq[j], ofs);
        }
    }
    if (lane < 4) {
        #pragma unroll
        for (int nh = 0; nh < 2; nh++)
            #pragma unroll
            for (int n4 = 0; n4 < 4; n4++)
                #pragma unroll
                for (int jj = 0; jj < 2; jj++) {
                    int col = wn * 64 + nh * 32 + n4 * 8 + 2 * lane + jj;
                    atomicAdd(&g_sum[col],   ssum[nh * 8 + n4 * 2 + jj]);
                    atomicAdd(&g_sumsq[col], ssq[nh * 8 + n4 * 2 + jj]);
                }
    }
}

// ------------------------- 3. BN coefficients (self-zeroing stats) ----------
__global__ void bn_coef_kernel(const float* __restrict__ gamma,
                               const float* __restrict__ beta, float invE) {
    int c = threadIdx.x;
    float s = g_sum[c], ss = g_sumsq[c];
    float mean = s * invE;
    float var  = fmaf(-mean, mean, ss * invE);
    float a    = gamma[c] * rsqrtf(var + BN_EPS);
    g_coef[c]        = a;
    g_coef[OUTC + c] = fmaf(-mean, a, beta[c]);
    g_sum[c] = 0.f;
    g_sumsq[c] = 0.f;
}

// ------------------------- 4. CSR gate: streaming z -------------------------
__global__ void __launch_bounds__(256)
csr_gate_kernel(const int* __restrict__ gidArr, int nNodes, int doPool) {
    int gw = blockIdx.x * 8 + (threadIdx.x >> 5);
    if (gw >= nNodes) return;
    int lane = threadIdx.x & 31;

    float sa0 = g_coef[2 * lane],             sa1 = g_coef[2 * lane + 1];
    float ha0 = g_coef[OUTC + 2 * lane],      ha1 = g_coef[OUTC + 2 * lane + 1];
    float sb0 = g_coef[64 + 2 * lane],        sb1 = g_coef[64 + 2 * lane + 1];
    float hb0 = g_coef[OUTC + 64 + 2 * lane], hb1 = g_coef[OUTC + 64 + 2 * lane + 1];

    int beg = g_rowstart[gw], end = g_rowstart[gw + 1];
    float a0 = 0.f, a1 = 0.f;
    const uint32_t* zr = (const uint32_t*)(g_zh) + (size_t)beg * 64;
    #pragma unroll 2
    for (int i = beg; i < end; i++, zr += 64) {
        uint32_t A = zr[lane], B = zr[32 + lane];
        __half2 ha = *reinterpret_cast<__half2*>(&A);
        __half2 hb = *reinterpret_cast<__half2*>(&B);
        float na0 = fmaf(__low2float(ha),  sa0, ha0);
        float na1 = fmaf(__high2float(ha), sa1, ha1);
        float nb0 = fmaf(__low2float(hb),  sb0, hb0);
        float nb1 = fmaf(__high2float(hb), sb1, hb1);
        a0 += fsig(na0) * fsp(nb0);
        a1 += fsig(na1) * fsp(nb1);
    }
    float2* hp = (float2*)(g_h + (size_t)gw * HDIM) + lane;
    float2 hv = *hp;
    hv.x += a0; hv.y += a1;
    *hp = hv;
    __half2 hh = __floats2half2_rn(hv.x, hv.y);
    g_hh[(size_t)gw * 32 + lane] = *reinterpret_cast<uint32_t*>(&hh);
    if (doPool) {
        int g = gidArr[gw];
        float* pr = g_pool + (size_t)g * HDIM + 2 * lane;
        asm volatile("red.global.add.v2.f32 [%0], {%1, %2};"
                     :: "l"(pr), "f"(hv.x), "f"(hv.y) : "memory");
        if (lane == 0) atomicAdd(&g_cnt[g], 1.0f);
    }
}

// ------------------------- 5. prediction head (self-zeroing pool) -----------
__global__ void __launch_bounds__(PRED_H)
head_kernel(const float* __restrict__ fcW, const float* __restrict__ fcb,
            const float* __restrict__ outW, const float* __restrict__ outb,
            float* __restrict__ out) {
    __shared__ float sp[HDIM];
    __shared__ float red[PRED_H];
    int g = blockIdx.x, t = threadIdx.x;
    if (t < HDIM) {
        float c = g_cnt[g];
        sp[t] = g_pool[(size_t)g * HDIM + t] / fmaxf(c, 1.0f);
    }
    __syncthreads();
    float acc = fcb[t];
    #pragma unroll
    for (int k = 0; k < HDIM; k++) acc = fmaf(sp[k], fcW[k * PRED_H + t], acc);
    red[t] = fmaxf(acc, 0.f) + log1pf(expf(-fabsf(acc)));
    red[t] *= outW[t];
    __syncthreads();
    for (int sft = PRED_H / 2; sft > 0; sft >>= 1) {
        if (t < sft) red[t] += red[t + sft];
        __syncthreads();
    }
    if (t == 0) out[g] = red[0] + outb[0];
    __syncthreads();
    if (t < HDIM) g_pool[(size_t)g * HDIM + t] = 0.f;
    if (t == HDIM) g_cnt[g] = 0.f;
}

// ------------------------- launch -------------------------------------------
extern "C" void kernel_launch(void* const* d_in, const int* in_sizes, int n_in,
                              void* d_out, int out_size) {
    const float* node_feats = (const float*)d_in[0];
    const int*   edge_index = (const int*)d_in[1];
    const float* edge_feats = (const float*)d_in[2];
    const int*   graph_id   = (const int*)d_in[3];
    const float* emb_W      = (const float*)d_in[4];
    const float* emb_b      = (const float*)d_in[5];
    const float* conv_W     = (const float*)d_in[6];
    // d_in[7] = conv_b: zeros; constant bias cancels exactly in BN.
    const float* bn_gamma   = (const float*)d_in[8];
    const float* bn_beta    = (const float*)d_in[9];
    const float* fc_W       = (const float*)d_in[10];
    const float* fc_b       = (const float*)d_in[11];
    const float* out_W      = (const float*)d_in[12];
    const float* out_b      = (const float*)d_in[13];

    int nNodes  = in_sizes[0] / NODE_DIM;
    int nEdges  = in_sizes[1] / 2;
    int nConv   = in_sizes[6] / (KD * OUTC);

    int nsm = 148;
    cudaDeviceGetAttribute(&nsm, cudaDevAttrMultiProcessorCount, 0);

    size_t convSmem = (size_t)SMEM_WORDS * 4;   // 92160 B
    cudaFuncSetAttribute(conv_mma_kernel,
                         cudaFuncAttributeMaxDynamicSharedMemorySize, (int)convSmem);

    emb_kernel<<<2048, 256>>>(node_feats, emb_W, emb_b, nNodes);
    {
        long long tot = (long long)nEdges * 24;
        efsplit_kernel<<<(int)((tot + 255) / 256), 256>>>(edge_feats, nEdges);
    }

    // ---- CSR build (edge_index constant across layers) ----
    int eb = (nEdges + 255) / 256;
    int nb1 = (nNodes + 1023) / 1024;
    zero_cnt_kernel<<<(nNodes + 255) / 256, 256>>>(nNodes);
    hist_kernel<<<eb, 256>>>(edge_index, nEdges);
    scan1_kernel<<<nb1, 1024>>>(nNodes);
    scan2_kernel<<<1, 1024>>>(nb1);
    scan3_kernel<<<nb1, 1024>>>(nNodes, nEdges);
    scatter_kernel<<<eb, 256>>>(edge_index, nEdges);

    // ---- all-layer B fragments ----
    bfrag_kernel<<<(nConv * BU2 + 255) / 256, 256>>>(conv_W, nConv * BU2);

    int nTiles = (nEdges + 127) / 128;
    float invE = 1.0f / (float)nEdges;
    int gateBlocks = (nNodes + 7) / 8;
    for (int l = 0; l < nConv; l++) {
        conv_mma_kernel<<<2 * nsm, 256, convSmem>>>(edge_index, l, nEdges, nTiles);
        bn_coef_kernel<<<1, OUTC>>>(bn_gamma + l * OUTC, bn_beta + l * OUTC, invE);
        csr_gate_kernel<<<gateBlocks, 256>>>(graph_id, nNodes, l == nConv - 1);
    }

    head_kernel<<<out_size, PRED_H>>>(fc_W, fc_b, out_W, out_b, (float*)d_out);
}